// round 1
// baseline (speedup 1.0000x reference)
#include <cuda_runtime.h>
#include <cstdint>

#define NH       4096
#define OBS      512
#define NTP      64
#define NSTEPS   (NTP - 1)          // 63
#define NOUT     128                // 2 * latent_dim
#define GRID     147
#define RPB      28                 // rows per block (147*28 = 4116 >= 4096)
#define SROWS    12                 // weight rows cached in SMEM per block
#define NTHREADS (RPB * 32)         // 896 threads = 28 warps
#define NH4      (NH / 4)           // 1024 float4 per row
#define CMB      (OBS + NH)         // 4608
#define CMB4     (CMB / 4)          // 1152

// dynamic smem: [SROWS*NH weights][CMB vector buffer]
#define SMEM_FLOATS (SROWS * NH + CMB)
#define SMEM_BYTES  (SMEM_FLOATS * 4)

// -------- device-global scratch (no allocations allowed) --------
__device__ __align__(16) float gV[2][NH];   // ping-pong stage input vector
__device__ __align__(16) float gHn[NH];     // h_new for h2o
__device__ unsigned g_arrive;               // zero-init
__device__ volatile unsigned g_gen;

// -------- grid-wide barrier (all GRID CTAs resident: smem forces 1 CTA/SM) ---
__device__ __forceinline__ void grid_sync() {
    __syncthreads();
    if (threadIdx.x == 0) {
        __threadfence();                       // publish my stores
        unsigned gen = g_gen;
        unsigned a = atomicAdd(&g_arrive, 1u);
        if (a == GRID - 1) {
            g_arrive = 0;                      // everyone else is spinning
            __threadfence();
            g_gen = gen + 1;                   // release
        } else {
            while (g_gen == gen) { }
            __threadfence();                   // acquire
        }
    }
    __syncthreads();
}

__device__ __forceinline__ float warp_reduce(float v) {
    #pragma unroll
    for (int o = 16; o; o >>= 1) v += __shfl_xor_sync(0xffffffffu, v, o);
    return v;
}

__global__ void __launch_bounds__(NTHREADS, 1)
ode_rnn_kernel(const float* __restrict__ x,
               const float* __restrict__ h0,
               const float* __restrict__ t,
               const float* __restrict__ Wf,
               const float* __restrict__ bf,
               const float* __restrict__ Wi,
               const float* __restrict__ bi,
               const float* __restrict__ Wo,
               const float* __restrict__ bo,
               float* __restrict__ out)
{
    extern __shared__ float smem[];
    float* wsm = smem;                 // SROWS * NH
    float* vsm = smem + SROWS * NH;    // CMB floats

    const int tid  = threadIdx.x;
    const int w    = tid >> 5;
    const int lane = tid & 31;
    const int base = blockIdx.x * RPB;
    const int row  = base + w;
    const bool active = (row < NH);

    // ---- preload SROWS contiguous weight rows into SMEM (one time) ----
    {
        const float4* src = (const float4*)(Wf + (size_t)base * NH);
        float4* dst = (float4*)wsm;
        int maxi = 0;
        if (base < NH) {
            int avail = NH - base;
            if (avail > SROWS) avail = SROWS;
            maxi = avail * NH4;
        }
        for (int i = tid; i < SROWS * NH4; i += NTHREADS)
            dst[i] = (i < maxi) ? __ldg(src + i) : make_float4(0.f, 0.f, 0.f, 0.f);
    }

    float hreg = 0.f, bfr = 0.f;
    if (active) {
        hreg = __ldg(h0 + row);
        bfr  = __ldg(bf + row);
        if (lane == 0) gV[0][row] = hreg;      // initial stage input = h
    }

    const float4* wrow_g = (const float4*)(Wf + (size_t)row * NH);  // gmem path
    const float4* wrow_s = (const float4*)(wsm + (size_t)w * NH);   // smem path
    const bool use_smem = (w < SROWS);

    int p = 0;
    grid_sync();   // gV[0] fully written

    float k1 = 0.f, k2 = 0.f, k3 = 0.f;

    for (int s = 0; s < NSTEPS; ++s) {
        const float dt = __ldg(t + s + 1) - __ldg(t + s);

        #pragma unroll
        for (int u = 0; u < 4; ++u) {
            // broadcast current stage-input vector into SMEM (L2-coherent reads)
            {
                const float4* src = (const float4*)gV[p];
                float4* dst = (float4*)vsm;
                for (int i = tid; i < NH4; i += NTHREADS)
                    dst[i] = __ldcg(src + i);
            }
            __syncthreads();

            if (active) {
                const float4* vv = (const float4*)vsm;
                float ax = 0.f, ay = 0.f, az = 0.f, aw = 0.f;
                if (use_smem) {
                    #pragma unroll 4
                    for (int i = lane; i < NH4; i += 32) {
                        float4 a = wrow_s[i];
                        float4 b = vv[i];
                        ax = fmaf(a.x, b.x, ax); ay = fmaf(a.y, b.y, ay);
                        az = fmaf(a.z, b.z, az); aw = fmaf(a.w, b.w, aw);
                    }
                } else {
                    #pragma unroll 4
                    for (int i = lane; i < NH4; i += 32) {
                        float4 a = __ldg(wrow_g + i);
                        float4 b = vv[i];
                        ax = fmaf(a.x, b.x, ax); ay = fmaf(a.y, b.y, ay);
                        az = fmaf(a.z, b.z, az); aw = fmaf(a.w, b.w, aw);
                    }
                }
                float z = warp_reduce((ax + ay) + (az + aw));
                float k = tanhf(z + bfr);

                float vn;
                if (u == 0)      { k1 = k; vn = hreg + (0.5f * dt) * k; }
                else if (u == 1) { k2 = k; vn = hreg + (0.5f * dt) * k; }
                else if (u == 2) { k3 = k; vn = hreg + dt * k; }
                else {
                    hreg = hreg + (dt * (1.0f / 6.0f)) * (k1 + 2.0f * k2 + 2.0f * k3 + k);
                    vn = hreg;
                }
                if (lane == 0) gV[p ^ 1][row] = vn;
            }
            grid_sync();
            p ^= 1;
        }
    }
    // gV[p] now holds hT; hreg holds hT for owned rows.

    // ---- i2h: h_new = tanh(W_i2h @ [x; hT] + b_i2h) ----
    {
        float4* dst = (float4*)vsm;
        const float4* xs = (const float4*)x;          // 128 float4
        const float4* hs = (const float4*)gV[p];      // 1024 float4
        for (int i = tid; i < CMB4; i += NTHREADS)
            dst[i] = (i < OBS / 4) ? __ldg(xs + i) : __ldcg(hs + (i - OBS / 4));
    }
    __syncthreads();

    if (active) {
        const float4* wr = (const float4*)(Wi + (size_t)row * CMB);
        const float4* vv = (const float4*)vsm;
        float ax = 0.f, ay = 0.f, az = 0.f, aw = 0.f;
        #pragma unroll 4
        for (int i = lane; i < CMB4; i += 32) {       // 36 iters
            float4 a = __ldg(wr + i);
            float4 b = vv[i];
            ax = fmaf(a.x, b.x, ax); ay = fmaf(a.y, b.y, ay);
            az = fmaf(a.z, b.z, az); aw = fmaf(a.w, b.w, aw);
        }
        float z = warp_reduce((ax + ay) + (az + aw));
        if (lane == 0) {
            float hn = tanhf(z + __ldg(bi + row));
            gHn[row] = hn;
            out[NOUT + row] = hn;                     // second tuple element
        }
    }
    grid_sync();

    // ---- h2o: out = W_h2o @ h_new + b_h2o (128 rows; CTAs 0..127, warp 0) ----
    if (blockIdx.x < NOUT && w == 0) {
        const int r = blockIdx.x;
        const float4* wr = (const float4*)(Wo + (size_t)r * NH);
        const float4* hv = (const float4*)gHn;
        float ax = 0.f, ay = 0.f, az = 0.f, aw = 0.f;
        #pragma unroll 4
        for (int i = lane; i < NH4; i += 32) {
            float4 a = __ldg(wr + i);
            float4 b = __ldcg(hv + i);
            ax = fmaf(a.x, b.x, ax); ay = fmaf(a.y, b.y, ay);
            az = fmaf(a.z, b.z, az); aw = fmaf(a.w, b.w, aw);
        }
        float z = warp_reduce((ax + ay) + (az + aw));
        if (lane == 0) out[r] = z + __ldg(bo + r);
    }
}

extern "C" void kernel_launch(void* const* d_in, const int* in_sizes, int n_in,
                              void* d_out, int out_size)
{
    const float* x   = (const float*)d_in[0];   // (1, 512)
    const float* h0  = (const float*)d_in[1];   // (4096,)
    const float* t   = (const float*)d_in[2];   // (64,)
    const float* Wf  = (const float*)d_in[3];   // (4096, 4096)
    const float* bf  = (const float*)d_in[4];   // (4096,)
    const float* Wi  = (const float*)d_in[5];   // (4096, 4608)
    const float* bi  = (const float*)d_in[6];   // (4096,)
    const float* Wo  = (const float*)d_in[7];   // (128, 4096)
    const float* bo  = (const float*)d_in[8];   // (128,)
    float* out = (float*)d_out;                 // 128 + 4096 = 4224 floats

    cudaFuncSetAttribute(ode_rnn_kernel,
                         cudaFuncAttributeMaxDynamicSharedMemorySize, SMEM_BYTES);
    ode_rnn_kernel<<<GRID, NTHREADS, SMEM_BYTES>>>(x, h0, t, Wf, bf, Wi, bi, Wo, bo, out);
}

// round 2
// speedup vs baseline: 1.1449x; 1.1449x over previous
#include <cuda_runtime.h>
#include <cstdint>

#define NH       4096
#define NH4      1024
#define OBS      512
#define NSTEPS   63
#define NOUT     128
#define CMB      4608
#define CMB4     1152

#define GRID     147
#define NW       7                    // warps per CTA
#define NTHREADS (NW * 32)            // 224
#define RPB      28                   // rows per CTA (4 per warp)
#define SW       13                   // weight rows cached in SMEM

// dynamic smem: [SW rows of Wf][NH-float v buffer] = 229376 B (< 232448 cap)
#define SMEM_BYTES ((SW * NH + NH) * 4)

__device__ __align__(16) float gV[2][NH];   // stage-input ping-pong
__device__ __align__(16) float gHn[NH];     // h_new
__device__ unsigned g_arrive;
__device__ volatile unsigned g_gen;

__device__ __forceinline__ void grid_sync() {
    __syncthreads();
    if (threadIdx.x == 0) {
        __threadfence();
        unsigned gen = g_gen;
        unsigned a = atomicAdd(&g_arrive, 1u);
        if (a == GRID - 1) {
            g_arrive = 0;
            __threadfence();
            g_gen = gen + 1;
        } else {
            while (g_gen == gen) { }
            __threadfence();
        }
    }
    __syncthreads();
}

__device__ __forceinline__ float warp_sum(float v) {
    #pragma unroll
    for (int o = 16; o; o >>= 1) v += __shfl_xor_sync(0xffffffffu, v, o);
    return v;
}

#define FMA4(A, Q, B) \
    { (A).x = fmaf((Q).x, (B).x, (A).x); (A).y = fmaf((Q).y, (B).y, (A).y); \
      (A).z = fmaf((Q).z, (B).z, (A).z); (A).w = fmaf((Q).w, (B).w, (A).w); }

__global__ void __launch_bounds__(NTHREADS, 1)
ode_rnn_kernel(const float* __restrict__ x,
               const float* __restrict__ h0,
               const float* __restrict__ t,
               const float* __restrict__ Wf,
               const float* __restrict__ bf,
               const float* __restrict__ Wi,
               const float* __restrict__ bi,
               const float* __restrict__ Wo,
               const float* __restrict__ bo,
               float* __restrict__ out)
{
    extern __shared__ float smem[];
    float4* wsm = (float4*)smem;                  // SW * NH4 float4
    float4* vsm = (float4*)(smem + SW * NH);      // NH4 float4

    const int tid  = threadIdx.x;
    const int w    = tid >> 5;
    const int lane = tid & 31;
    const int base = blockIdx.x * RPB;

    // warp w owns global rows r0..r3 = base+4w .. base+4w+3
    const int r0 = base + 4 * w;
    const int c0 = min(r0,     NH - 1);           // clamped (safe) indices
    const int c2 = min(r0 + 2, NH - 1);
    const int c3 = min(r0 + 3, NH - 1);

    const float4* Wf4 = (const float4*)Wf;

    // ---- SMEM weight preload: 13 rows/CTA ----
    // slot s<12 -> local row (s/2)*4 + 1 + (s&1)  (rows 4w+1, 4w+2 for w<6)
    // slot 12   -> local row 25                    (row 4*6+1 for w==6)
    for (int idx = tid; idx < SW * NH4; idx += NTHREADS) {
        int slot   = idx >> 10;
        int within = idx & 1023;
        int lr     = (slot < 12) ? ((slot >> 1) << 2) + 1 + (slot & 1) : 25;
        int gr     = min(base + lr, NH - 1);
        wsm[idx]   = __ldg(Wf4 + (size_t)gr * NH4 + within);
    }

    // ---- register-cache row r0 (one full row per warp) ----
    float4 wreg[32];
    {
        const float4* p = Wf4 + (size_t)c0 * NH4 + lane;
        #pragma unroll
        for (int k = 0; k < 32; ++k) wreg[k] = __ldg(p + 32 * k);
    }

    // per-lane RK4 state: lane j (<4) owns row r0+j
    float hh = 0.f, bfv = 0.f;
    if (lane < 4) {
        int r = min(r0 + lane, NH - 1);
        hh  = __ldg(h0 + r);
        bfv = __ldg(bf + r);
        if (r0 + lane < NH) gV[0][r0 + lane] = hh;
    }

    // per-warp source pointers for rows 1..3
    const float4* ws1 = wsm + (size_t)((w < 6) ? (2 * w) : 12) * NH4;   // row r0+1 (SMEM)
    const float4* ws2 = wsm + (size_t)((w < 6) ? (2 * w + 1) : 0) * NH4; // row r0+2 (SMEM, w<6)
    const float4* wg2 = Wf4 + (size_t)c2 * NH4;                         // row r0+2 (L2, w==6)
    const float4* wg3 = Wf4 + (size_t)c3 * NH4;                         // row r0+3 (L2)

    int p = 0;
    grid_sync();   // gV[0] complete

    float k1 = 0.f, k2 = 0.f, k3 = 0.f;

    for (int s = 0; s < NSTEPS; ++s) {
        const float dt   = __ldg(t + s + 1) - __ldg(t + s);
        const float half = 0.5f * dt;

        #pragma unroll 1
        for (int u = 0; u < 4; ++u) {
            // stage-input broadcast into SMEM (coherent L2 reads)
            {
                const float4* src = (const float4*)gV[p];
                for (int i = tid; i < NH4; i += NTHREADS)
                    vsm[i] = __ldcg(src + i);
            }
            __syncthreads();

            float4 A0 = make_float4(0.f,0.f,0.f,0.f);
            float4 A1 = A0, A2 = A0, A3 = A0;

            if (w < 6) {
                #pragma unroll
                for (int k = 0; k < 32; ++k) {
                    const int i = lane + 32 * k;
                    float4 b  = vsm[i];
                    float4 q3 = __ldg(wg3 + i);     // L2 row issued early
                    float4 q1 = ws1[i];
                    float4 q2 = ws2[i];
                    FMA4(A0, wreg[k], b);
                    FMA4(A1, q1, b);
                    FMA4(A2, q2, b);
                    FMA4(A3, q3, b);
                }
            } else {
                #pragma unroll
                for (int k = 0; k < 32; ++k) {
                    const int i = lane + 32 * k;
                    float4 b  = vsm[i];
                    float4 q2 = __ldg(wg2 + i);
                    float4 q3 = __ldg(wg3 + i);
                    float4 q1 = ws1[i];
                    FMA4(A0, wreg[k], b);
                    FMA4(A1, q1, b);
                    FMA4(A2, q2, b);
                    FMA4(A3, q3, b);
                }
            }

            float z0 = warp_sum((A0.x + A0.y) + (A0.z + A0.w));
            float z1 = warp_sum((A1.x + A1.y) + (A1.z + A1.w));
            float z2 = warp_sum((A2.x + A2.y) + (A2.z + A2.w));
            float z3 = warp_sum((A3.x + A3.y) + (A3.z + A3.w));

            // lane j handles row r0+j
            float z  = (lane == 0) ? z0 : (lane == 1) ? z1 : (lane == 2) ? z2 : z3;
            float kk = tanhf(z + bfv);

            float vn;
            if (u == 0)      { k1 = kk; vn = hh + half * kk; }
            else if (u == 1) { k2 = kk; vn = hh + half * kk; }
            else if (u == 2) { k3 = kk; vn = hh + dt * kk; }
            else {
                hh = hh + (dt * (1.0f / 6.0f)) * (k1 + 2.0f * k2 + 2.0f * k3 + kk);
                vn = hh;
            }
            if (lane < 4 && (r0 + lane) < NH) gV[p ^ 1][r0 + lane] = vn;

            grid_sync();
            p ^= 1;
        }
    }
    // gV[p] == hT

    // ---- i2h: h_new = tanh(W_i2h @ [x; hT] + b_i2h) ----
    {
        float4* cmb = (float4*)smem;                 // reuse weight SMEM
        const float4* xs = (const float4*)x;
        const float4* hs = (const float4*)gV[p];
        for (int i = tid; i < CMB4; i += NTHREADS)
            cmb[i] = (i < OBS / 4) ? __ldg(xs + i) : __ldcg(hs + (i - OBS / 4));
        __syncthreads();

        const float4* Wi4 = (const float4*)Wi;
        const float4* p0 = Wi4 + (size_t)c0 * CMB4;
        const float4* p1 = Wi4 + (size_t)min(r0 + 1, NH - 1) * CMB4;
        const float4* p2 = Wi4 + (size_t)c2 * CMB4;
        const float4* p3 = Wi4 + (size_t)c3 * CMB4;

        float4 A0 = make_float4(0.f,0.f,0.f,0.f);
        float4 A1 = A0, A2 = A0, A3 = A0;
        #pragma unroll 4
        for (int k = 0; k < 36; ++k) {               // CMB4/32 = 36
            const int i = lane + 32 * k;
            float4 b = cmb[i];
            FMA4(A0, __ldg(p0 + i), b);
            FMA4(A1, __ldg(p1 + i), b);
            FMA4(A2, __ldg(p2 + i), b);
            FMA4(A3, __ldg(p3 + i), b);
        }
        float z0 = warp_sum((A0.x + A0.y) + (A0.z + A0.w));
        float z1 = warp_sum((A1.x + A1.y) + (A1.z + A1.w));
        float z2 = warp_sum((A2.x + A2.y) + (A2.z + A2.w));
        float z3 = warp_sum((A3.x + A3.y) + (A3.z + A3.w));

        if (lane < 4) {
            int r = r0 + lane;
            if (r < NH) {
                float z  = (lane == 0) ? z0 : (lane == 1) ? z1 : (lane == 2) ? z2 : z3;
                float hn = tanhf(z + __ldg(bi + r));
                gHn[r] = hn;
                out[NOUT + r] = hn;
            }
        }
    }
    grid_sync();

    // ---- h2o: out[0..127] = W_h2o @ h_new + b_h2o (one row per warp) ----
    {
        const int gw = blockIdx.x * NW + w;
        if (gw < NOUT) {
            const float4* wr = (const float4*)Wo + (size_t)gw * NH4;
            const float4* hv = (const float4*)gHn;
            float4 A = make_float4(0.f,0.f,0.f,0.f);
            #pragma unroll 4
            for (int k = 0; k < 32; ++k) {
                const int i = lane + 32 * k;
                FMA4(A, __ldg(wr + i), __ldcg(hv + i));
            }
            float z = warp_sum((A.x + A.y) + (A.z + A.w));
            if (lane == 0) out[gw] = z + __ldg(bo + gw);
        }
    }
}

extern "C" void kernel_launch(void* const* d_in, const int* in_sizes, int n_in,
                              void* d_out, int out_size)
{
    const float* x   = (const float*)d_in[0];
    const float* h0  = (const float*)d_in[1];
    const float* t   = (const float*)d_in[2];
    const float* Wf  = (const float*)d_in[3];
    const float* bf  = (const float*)d_in[4];
    const float* Wi  = (const float*)d_in[5];
    const float* bi  = (const float*)d_in[6];
    const float* Wo  = (const float*)d_in[7];
    const float* bo  = (const float*)d_in[8];
    float* out = (float*)d_out;

    cudaFuncSetAttribute(ode_rnn_kernel,
                         cudaFuncAttributeMaxDynamicSharedMemorySize, SMEM_BYTES);
    ode_rnn_kernel<<<GRID, NTHREADS, SMEM_BYTES>>>(x, h0, t, Wf, bf, Wi, bi, Wo, bo, out);
}